// round 5
// baseline (speedup 1.0000x reference)
#include <cuda_runtime.h>

#define BB 64
#define TT 8000
#define SS 10
#define CHUNKS 9
#define ROWSPC ((TT + CHUNKS - 1) / CHUNKS)   // 889
#define NACC 110                              // 100 sel + 10 tot
#define FULL 0xFFFFFFFFu
#define FLT_MAX_C 3.402823466e+38f
#define LN2F 0.69314718055994530942f

// Scratch (no allocations allowed). Zero-initialized device globals.
__device__ float    g_part[BB * CHUNKS * NACC];
__device__ double   g_bsum[BB];
__device__ unsigned g_ticket2;

// ---------------------------------------------------------------------------
// Kernel 1: pairwise BCE partial reduction (round-3 proven config).
// 576 blocks x 256 threads, 4 blocks/SM. Each warp owns one (ihalf, jhalf)
// class of the 10x10 outer product; accumulates in lg2 units (x ln2 once).
// ---------------------------------------------------------------------------
template <int IH, int JH>
__device__ __forceinline__ void pw_body(const float* __restrict__ pred,
                                        const float* __restrict__ tgt,
                                        int b, int t0, int tend, int slot,
                                        float sel[5][5], float tot[5]) {
    for (int t = t0 + slot; t < tend; t += 64) {
        const size_t base = ((size_t)b * TT + (size_t)t) * SS;
        const float2* pp = reinterpret_cast<const float2*>(pred + base + IH * 4);
        const float2* tp = reinterpret_cast<const float2*>(tgt  + base + JH * 4);
        const float2 p0 = pp[0], p1 = pp[1], p2 = pp[2];
        const float2 q0 = tp[0], q1 = tp[1], q2 = tp[2];
        const float pe[6] = {p0.x, p0.y, p1.x, p1.y, p2.x, p2.y};
        const float te[6] = {q0.x, q0.y, q1.x, q1.y, q2.x, q2.y};

        float diff[5];
#pragma unroll
        for (int ii = 0; ii < 5; ii++) {
            const float p  = pe[ii + IH];          // static index
            const float l1 = __log2f(p);           // lg2(p)
            const float l2 = __log2f(1.0f - p);    // lg2(1-p); p in [0.01, 0.99]
            diff[ii] = l1 - l2;
            tot[ii] += l2;
        }
#pragma unroll
        for (int jj = 0; jj < 5; jj++) {
            const float tj = te[jj + JH];          // exactly 0.0f or 1.0f
#pragma unroll
            for (int ii = 0; ii < 5; ii++)
                sel[ii][jj] = fmaf(diff[ii], tj, sel[ii][jj]);
        }
    }
}

__global__ __launch_bounds__(256, 4) void pairwise_kernel(const float* __restrict__ pred,
                                                          const float* __restrict__ tgt) {
    const int b    = blockIdx.x / CHUNKS;
    const int c    = blockIdx.x % CHUNKS;
    const int tid  = threadIdx.x;
    const int slot = tid & 63;
    const int w    = tid >> 5;
    const int q    = w >> 1;                  // warp-uniform class: ihalf=q&1, jhalf=q>>1

    const int t0   = c * ROWSPC;
    const int tend = (t0 + ROWSPC < TT) ? (t0 + ROWSPC) : TT;

    float sel[5][5];
    float tot[5];
#pragma unroll
    for (int ii = 0; ii < 5; ii++) {
        tot[ii] = 0.0f;
#pragma unroll
        for (int jj = 0; jj < 5; jj++) sel[ii][jj] = 0.0f;
    }

    switch (q) {
        case 0: pw_body<0, 0>(pred, tgt, b, t0, tend, slot, sel, tot); break;
        case 1: pw_body<1, 0>(pred, tgt, b, t0, tend, slot, sel, tot); break;
        case 2: pw_body<0, 1>(pred, tgt, b, t0, tend, slot, sel, tot); break;
        default: pw_body<1, 1>(pred, tgt, b, t0, tend, slot, sel, tot); break;
    }

    // Full-warp tree reduction of the 30 accumulators -> lane 0.
#pragma unroll
    for (int ii = 0; ii < 5; ii++) {
#pragma unroll
        for (int jj = 0; jj < 5; jj++) {
            float v = sel[ii][jj];
#pragma unroll
            for (int o = 16; o; o >>= 1) v += __shfl_down_sync(FULL, v, o);
            sel[ii][jj] = v;
        }
        float v = tot[ii];
#pragma unroll
        for (int o = 16; o; o >>= 1) v += __shfl_down_sync(FULL, v, o);
        tot[ii] = v;
    }

    __shared__ float s[8][30];
    const int lane = tid & 31;
    if (lane == 0) {
#pragma unroll
        for (int ii = 0; ii < 5; ii++) {
#pragma unroll
            for (int jj = 0; jj < 5; jj++) s[w][ii * 5 + jj] = sel[ii][jj];
            s[w][25 + ii] = tot[ii];
        }
    }
    __syncthreads();

    if (tid < NACC) {
        int qq, idx;
        if (tid < 100) {
            const int i = tid / 10, j = tid % 10;
            const int ih = (i >= 5), jh = (j >= 5);
            qq  = jh * 2 + ih;
            idx = (i % 5) * 5 + (j % 5);
        } else {
            const int i = tid - 100;
            const int ih = (i >= 5);
            qq  = ih;                      // tot kept only by jhalf==0 classes
            idx = 25 + (i % 5);
        }
        g_part[(b * CHUNKS + c) * NACC + tid] =
            (s[2 * qq][idx] + s[2 * qq + 1][idx]) * LN2F;   // lg2 -> ln once
    }
}

// ---------------------------------------------------------------------------
// Kernel 2: block-per-batch Hungarian, SERIAL single-thread JV (n=10).
// 128 threads do the coalesced cost build; thread 0 runs JV with all state in
// registers (constant-indexed arrays; p packed as nibbles; way via select
// chains). JV warm start (row/col reduction) shortens augmenting paths; the
// optimal total cost -- and hence the output mean -- is unchanged.
// ---------------------------------------------------------------------------
__device__ __forceinline__ int nib_get(unsigned long long x, int i) {
    return (int)((x >> (i * 4)) & 15ull);
}
__device__ __forceinline__ unsigned long long nib_set(unsigned long long x, int i, int val) {
    const int s = i * 4;
    return (x & ~(15ull << s)) | ((unsigned long long)val << s);
}

__global__ __launch_bounds__(128) void hungarian_kernel(float* __restrict__ out) {
    __shared__ float s_cost[100];
    const int b   = blockIdx.x;
    const int tid = threadIdx.x;

    // Coalesced cost build from chunk partials.
    if (tid < 100) {
        const int i = tid / 10;
        float sl = 0.0f, to = 0.0f;
#pragma unroll
        for (int c = 0; c < CHUNKS; c++) {
            const float* gp = &g_part[(b * CHUNKS + c) * NACC];
            sl += __ldcg(&gp[tid]);
            to += __ldcg(&gp[100 + i]);
        }
        s_cost[tid] = -(to + sl) * (1.0f / (float)TT);
    }
    __syncthreads();
    if (tid != 0) return;

    // ---- Serial JV, all state in registers ----
    float u[SS], v[SS], minv[SS];
    int   wayv[SS];
    unsigned long long p64 = 0ull;      // p[0..10] nibbles, 0 = unassigned

    // Warm start: v[j] = min_i cost[i][j]; u[i] = min_j (cost[i][j] - v[j]).
#pragma unroll
    for (int j = 0; j < SS; j++) {
        float mn = s_cost[j];
#pragma unroll
        for (int i = 1; i < SS; i++) mn = fminf(mn, s_cost[i * 10 + j]);
        v[j] = mn;
    }
#pragma unroll
    for (int i = 0; i < SS; i++) {
        float mn = s_cost[i * 10] - v[0];
#pragma unroll
        for (int j = 1; j < SS; j++) mn = fminf(mn, s_cost[i * 10 + j] - v[j]);
        u[i] = mn;
    }

    for (int root = 1; root <= SS; root++) {
        p64 = nib_set(p64, 0, root);                // p[0] = root
#pragma unroll
        for (int j = 0; j < SS; j++) minv[j] = FLT_MAX_C;
        unsigned used = 1u;                          // virtual column 0
        unsigned rowm = 0u;
        int   j0 = 0;
        int   i0 = root;
        float u0 = 0.0f;
#pragma unroll
        for (int i = 1; i <= SS; i++) if (i0 == i) u0 = u[i - 1];

        while (true) {
            rowm |= 1u << i0;
            const int rb = (i0 - 1) * 10;

            // j-scan: 10 independent LDS + predicated updates.
#pragma unroll
            for (int j = 1; j <= SS; j++) {
                const float cur = s_cost[rb + (j - 1)] - u0 - v[j - 1];
                if (!((used >> j) & 1u) && cur < minv[j - 1]) {
                    minv[j - 1] = cur;
                    wayv[j - 1] = j0;
                }
            }

            // min + lowest-j argmin over unused columns (tree, short depth).
            float tmp[SS];
#pragma unroll
            for (int j = 1; j <= SS; j++)
                tmp[j - 1] = ((used >> j) & 1u) ? FLT_MAX_C : minv[j - 1];
            float delta = tmp[0];
#pragma unroll
            for (int j = 1; j < SS; j++) delta = fminf(delta, tmp[j]);
            unsigned bits = 0u;
#pragma unroll
            for (int j = 1; j <= SS; j++) bits |= (tmp[j - 1] == delta) ? (1u << j) : 0u;
            const int j1 = __ffs(bits) - 1;          // lowest j (ref tie-break)

            // Dual updates.
#pragma unroll
            for (int j = 1; j <= SS; j++) {
                if ((used >> j) & 1u) v[j - 1] -= delta;
                else                  minv[j - 1] -= delta;
            }
#pragma unroll
            for (int i = 1; i <= SS; i++)
                if ((rowm >> i) & 1u) u[i - 1] += delta;

            j0 = j1;
            used |= 1u << j0;
            const int pn = nib_get(p64, j0);
            if (pn == 0) break;
            i0 = pn;
#pragma unroll
            for (int i = 1; i <= SS; i++) if (i0 == i) u0 = u[i - 1];
        }

        // Augment along the alternating path.
        while (j0) {
            int jp = 0;
#pragma unroll
            for (int j = 1; j <= SS; j++) if (j0 == j) jp = wayv[j - 1];
            p64 = nib_set(p64, j0, nib_get(p64, jp));
            j0 = jp;
        }
    }

    // Matched sum for this batch (f64 accumulate of exact f32 cost entries).
    double val = 0.0;
#pragma unroll
    for (int j = 1; j <= SS; j++) {
        const int pj = nib_get(p64, j);
        val += (double)s_cost[(pj - 1) * 10 + (j - 1)];
    }
    g_bsum[b] = val;

    // Fused finalize: last block computes the mean.
    __threadfence();
    const unsigned t2 = atomicAdd(&g_ticket2, 1u);
    if (t2 == BB - 1) {
        g_ticket2 = 0;                               // reset for graph replay
        __threadfence();
        double acc[8];
#pragma unroll
        for (int k = 0; k < 8; k++) acc[k] = 0.0;
#pragma unroll
        for (int k = 0; k < BB; k++) acc[k & 7] += __ldcg(&g_bsum[k]);
        double x = ((acc[0] + acc[1]) + (acc[2] + acc[3])) +
                   ((acc[4] + acc[5]) + (acc[6] + acc[7]));
        out[0] = (float)(x / (double)(BB * SS));
    }
}

extern "C" void kernel_launch(void* const* d_in, const int* in_sizes, int n_in,
                              void* d_out, int out_size) {
    const float* pred = (const float*)d_in[0];
    const float* tgt  = (const float*)d_in[1];
    pairwise_kernel<<<BB * CHUNKS, 256>>>(pred, tgt);
    hungarian_kernel<<<BB, 128>>>((float*)d_out);
}

// round 6
// speedup vs baseline: 1.5619x; 1.5619x over previous
#include <cuda_runtime.h>

#define BB 64
#define TT 8000
#define SS 10
#define CHUNKS 9
#define ROWSPC ((TT + CHUNKS - 1) / CHUNKS)   // 889
#define NACC 110                              // 100 sel + 10 tot
#define FULL 0xFFFFFFFFu
#define FLT_MAX_C 3.402823466e+38f
#define LN2F 0.69314718055994530942f

// Scratch (no allocations allowed). Zero-initialized device globals.
__device__ float    g_part[BB * CHUNKS * NACC];
__device__ double   g_bsum[BB];
__device__ unsigned g_ticket2;

__device__ __forceinline__ unsigned enc_f32(float x) {
    unsigned b = __float_as_uint(x);
    return (b & 0x80000000u) ? ~b : (b | 0x80000000u);
}
__device__ __forceinline__ float dec_f32(unsigned e) {
    unsigned b = (e & 0x80000000u) ? (e & 0x7FFFFFFFu) : ~e;
    return __uint_as_float(b);
}

// 10-way register select, 4-deep tree (idx in 0..9).
__device__ __forceinline__ float sel10(const float w[SS], int idx) {
    const float x01 = (idx & 1) ? w[1] : w[0];
    const float x23 = (idx & 1) ? w[3] : w[2];
    const float x45 = (idx & 1) ? w[5] : w[4];
    const float x67 = (idx & 1) ? w[7] : w[6];
    const float x89 = (idx & 1) ? w[9] : w[8];
    const float y03 = (idx & 2) ? x23 : x01;
    const float y47 = (idx & 2) ? x67 : x45;
    const float z07 = (idx & 4) ? y47 : y03;
    return (idx & 8) ? x89 : z07;
}

// ---------------------------------------------------------------------------
// Kernel 1: pairwise BCE partial reduction (proven r3 config, lg2 units).
// ---------------------------------------------------------------------------
template <int IH, int JH>
__device__ __forceinline__ void pw_body(const float* __restrict__ pred,
                                        const float* __restrict__ tgt,
                                        int b, int t0, int tend, int slot,
                                        float sel[5][5], float tot[5]) {
    for (int t = t0 + slot; t < tend; t += 64) {
        const size_t base = ((size_t)b * TT + (size_t)t) * SS;
        const float2* pp = reinterpret_cast<const float2*>(pred + base + IH * 4);
        const float2* tp = reinterpret_cast<const float2*>(tgt  + base + JH * 4);
        const float2 p0 = pp[0], p1 = pp[1], p2 = pp[2];
        const float2 q0 = tp[0], q1 = tp[1], q2 = tp[2];
        const float pe[6] = {p0.x, p0.y, p1.x, p1.y, p2.x, p2.y};
        const float te[6] = {q0.x, q0.y, q1.x, q1.y, q2.x, q2.y};

        float diff[5];
#pragma unroll
        for (int ii = 0; ii < 5; ii++) {
            const float p  = pe[ii + IH];          // static index
            const float l1 = __log2f(p);           // lg2(p)
            const float l2 = __log2f(1.0f - p);    // lg2(1-p); p in [0.01, 0.99]
            diff[ii] = l1 - l2;
            tot[ii] += l2;
        }
#pragma unroll
        for (int jj = 0; jj < 5; jj++) {
            const float tj = te[jj + JH];          // exactly 0.0f or 1.0f
#pragma unroll
            for (int ii = 0; ii < 5; ii++)
                sel[ii][jj] = fmaf(diff[ii], tj, sel[ii][jj]);
        }
    }
}

__global__ __launch_bounds__(256, 4) void pairwise_kernel(const float* __restrict__ pred,
                                                          const float* __restrict__ tgt) {
    const int b    = blockIdx.x / CHUNKS;
    const int c    = blockIdx.x % CHUNKS;
    const int tid  = threadIdx.x;
    const int slot = tid & 63;
    const int w    = tid >> 5;
    const int q    = w >> 1;

    const int t0   = c * ROWSPC;
    const int tend = (t0 + ROWSPC < TT) ? (t0 + ROWSPC) : TT;

    float sel[5][5];
    float tot[5];
#pragma unroll
    for (int ii = 0; ii < 5; ii++) {
        tot[ii] = 0.0f;
#pragma unroll
        for (int jj = 0; jj < 5; jj++) sel[ii][jj] = 0.0f;
    }

    switch (q) {
        case 0: pw_body<0, 0>(pred, tgt, b, t0, tend, slot, sel, tot); break;
        case 1: pw_body<1, 0>(pred, tgt, b, t0, tend, slot, sel, tot); break;
        case 2: pw_body<0, 1>(pred, tgt, b, t0, tend, slot, sel, tot); break;
        default: pw_body<1, 1>(pred, tgt, b, t0, tend, slot, sel, tot); break;
    }

#pragma unroll
    for (int ii = 0; ii < 5; ii++) {
#pragma unroll
        for (int jj = 0; jj < 5; jj++) {
            float v = sel[ii][jj];
#pragma unroll
            for (int o = 16; o; o >>= 1) v += __shfl_down_sync(FULL, v, o);
            sel[ii][jj] = v;
        }
        float v = tot[ii];
#pragma unroll
        for (int o = 16; o; o >>= 1) v += __shfl_down_sync(FULL, v, o);
        tot[ii] = v;
    }

    __shared__ float s[8][30];
    const int lane = tid & 31;
    if (lane == 0) {
#pragma unroll
        for (int ii = 0; ii < 5; ii++) {
#pragma unroll
            for (int jj = 0; jj < 5; jj++) s[w][ii * 5 + jj] = sel[ii][jj];
            s[w][25 + ii] = tot[ii];
        }
    }
    __syncthreads();

    if (tid < NACC) {
        int qq, idx;
        if (tid < 100) {
            const int i = tid / 10, j = tid % 10;
            const int ih = (i >= 5), jh = (j >= 5);
            qq  = jh * 2 + ih;
            idx = (i % 5) * 5 + (j % 5);
        } else {
            const int i = tid - 100;
            const int ih = (i >= 5);
            qq  = ih;
            idx = 25 + (i % 5);
        }
        g_part[(b * CHUNKS + c) * NACC + tid] =
            (s[2 * qq][idx] + s[2 * qq + 1][idx]) * LN2F;
    }
}

// ---------------------------------------------------------------------------
// Kernel 2: warp-per-batch Hungarian (JV with warm start + greedy tight-edge
// pre-assignment). Lane j owns column j (cost column, v, minv, way, p); row
// potentials u are uniform registers in every lane. Inner loop critical path:
// REDUX.MIN -> ALU argmin -> 1 shuffle level -> register select tree.
// ---------------------------------------------------------------------------
__global__ __launch_bounds__(32) void hungarian_kernel(float* __restrict__ out) {
    __shared__ float s_cost[100];
    const int lane = threadIdx.x;
    const int b    = blockIdx.x;

    for (int k = lane; k < 100; k += 32) {
        const int i = k / 10;
        float sl = 0.0f, to = 0.0f;
#pragma unroll
        for (int c = 0; c < CHUNKS; c++) {
            const float* gp = &g_part[(b * CHUNKS + c) * NACC];
            sl += __ldcg(&gp[k]);
            to += __ldcg(&gp[100 + i]);
        }
        s_cost[k] = -(to + sl) * (1.0f / (float)TT);
    }
    __syncwarp();

    const bool isCol = (lane >= 1 && lane <= SS);
    const int  cl    = isCol ? (lane - 1) : 0;

    // Lane-resident cost column: colv[i] = cost[i][lane-1].
    float colv[SS];
#pragma unroll
    for (int i = 0; i < SS; i++) colv[i] = s_cost[i * 10 + cl];

    // Warm start: v[j] = min_i colv; u[i] = min_j (colv[i] - v) (uniform regs).
    float v = 0.0f;
    if (isCol) {
        float mn = colv[0];
#pragma unroll
        for (int i = 1; i < SS; i++) mn = fminf(mn, colv[i]);
        v = mn;
    }
    float uu[SS];
#pragma unroll
    for (int i = 0; i < SS; i++) {
        const float t = isCol ? (colv[i] - v) : FLT_MAX_C;
        uu[i] = dec_f32(__reduce_min_sync(FULL, enc_f32(t)));
    }

    // Greedy tight-edge pre-assignment: exact-zero reduced costs.
    int p = 0, way = 0;
    unsigned rowdone = 0u;
#pragma unroll
    for (int i = 1; i <= SS; i++) {
        const float red = isCol ? ((colv[i - 1] - v) - uu[i - 1]) : 1.0f;
        const bool  z   = isCol && (p == 0) && (red == 0.0f);
        const unsigned bal = __ballot_sync(FULL, z);
        if (bal) {
            const int j = __ffs(bal) - 1;
            if (lane == j) p = i;
            rowdone |= 1u << i;
        }
    }

    // Dijkstra for each remaining free row.
    for (int root = 1; root <= SS; root++) {
        if ((rowdone >> root) & 1u) continue;
        if (lane == 0) p = root;

        // Root-start snapshot: w[i] = (colv[i] - uu[i]) - v (valid while this
        // column is unused and row i unscanned -- exactly when it's consumed).
        float w[SS];
#pragma unroll
        for (int i = 0; i < SS; i++)
            w[i] = isCol ? ((colv[i] - uu[i]) - v) : FLT_MAX_C;

        float minv = FLT_MAX_C;
        unsigned used = 1u;            // virtual column 0
        unsigned rowm = 0u;
        int j0 = 0, i0 = root;

        while (true) {
            rowm |= 1u << i0;

            const bool  active = isCol && !((used >> lane) & 1u);
            const float cur    = sel10(w, i0 - 1);
            if (active && cur < minv) { minv = cur; way = j0; }

            const unsigned key = active ? ((enc_f32(minv) & 0xFFFFFFE0u) | (unsigned)lane)
                                        : 0xFFFFFFFFu;
            const unsigned m   = __reduce_min_sync(FULL, key);
            const int      j1  = (int)(m & 31u);
            const float delta  = __shfl_sync(FULL, minv, j1);   // exact winner value
            const int   pn     = __shfl_sync(FULL, p, j1);      // next row (0 = free)

            if (isCol) {
                if ((used >> lane) & 1u) v -= delta;
                else                     minv -= delta;
            }
#pragma unroll
            for (int i = 1; i <= SS; i++)
                if ((rowm >> i) & 1u) uu[i - 1] += delta;       // uniform

            used |= 1u << j1;
            j0 = j1;
            if (pn == 0) break;
            i0 = pn;
        }

        // Augment along the alternating path.
        while (j0) {
            const int jprev = __shfl_sync(FULL, way, j0);
            const int pprev = __shfl_sync(FULL, p, jprev);
            if (lane == j0) p = pprev;
            j0 = jprev;
        }
    }

    // Matched sum (exact f32 cost entries, f64 accumulate).
    double val = 0.0;
    if (isCol) val = (double)s_cost[(p - 1) * 10 + cl];
#pragma unroll
    for (int o = 16; o; o >>= 1) val += __shfl_down_sync(FULL, val, o);
    if (lane == 0) g_bsum[b] = val;

    // Fused finalize: last block computes the mean.
    __threadfence();
    unsigned t2 = 0;
    if (lane == 0) t2 = atomicAdd(&g_ticket2, 1u);
    t2 = __shfl_sync(FULL, t2, 0);
    if (t2 == BB - 1) {
        if (lane == 0) g_ticket2 = 0;              // reset for graph replay
        __threadfence();
        double x = __ldcg(&g_bsum[lane]) + __ldcg(&g_bsum[lane + 32]);
#pragma unroll
        for (int o = 16; o; o >>= 1) x += __shfl_down_sync(FULL, x, o);
        if (lane == 0) out[0] = (float)(x / (double)(BB * SS));
    }
}

extern "C" void kernel_launch(void* const* d_in, const int* in_sizes, int n_in,
                              void* d_out, int out_size) {
    const float* pred = (const float*)d_in[0];
    const float* tgt  = (const float*)d_in[1];
    pairwise_kernel<<<BB * CHUNKS, 256>>>(pred, tgt);
    hungarian_kernel<<<BB, 32>>>((float*)d_out);
}